// round 7
// baseline (speedup 1.0000x reference)
#include <cuda_runtime.h>
#include <cstdint>
#include <cstddef>

#define Bq 32
#define Sq 100
#define Tq 100
#define Eq 512
#define Hq 512
#define G4 2048   // 4H
#define H2 1024   // 2H
#define H3 1536   // 3H
#define VTq 32000

// ---------------- scratch (static device globals; no allocation) ----------------
__device__ float g_xsrc[Sq * Bq * Eq];            // gathered source embeddings [S,B,E]
__device__ float g_Xf[Sq * Bq * G4];              // fwd enc input gates [S,B,4H]
__device__ float g_Xb[Sq * Bq * G4];              // bwd enc input gates [S,B,4H]
__device__ float g_henc[2][2][Bq][Hq];            // [slot][dir][b][h] ping-pong
__device__ float g_cenc[2][Bq][Hq];               // [dir][b][h]
__device__ float g_encout[Bq][Sq][H2];            // [B,S,2H]
__device__ float g_encT[Bq][H2][Sq];              // transposed for ctx reduction
__device__ float g_P[(size_t)Bq * Sq * H3];       // precomputed att layer1 (enc part)
__device__ float g_temb[Bq][Tq][Eq];
__device__ float g_temb_tb[Tq * Bq * Eq];         // [T,B,E]
__device__ float g_Xdec[Tq * Bq * G4];            // dec input gates (emb part) [T,B,4H]
__device__ float g_hdec[2][Bq][Hq];
__device__ float g_cdec[Bq][Hq];
__device__ float g_Qpart[16][Bq][H3];             // k-split partials of Q projection
__device__ float g_ctxs[Tq][Bq][H2];
__device__ float g_decs[Tq][Bq][Hq];
__device__ float g_clsin[(size_t)Bq * Tq * 2048];
__device__ float g_hid[(size_t)Bq * Tq * H2];

__device__ __forceinline__ float sigf(float x) { return 1.f / (1.f + __expf(-x)); }

__device__ __forceinline__ uint32_t f2tf(float x) {
    uint32_t r;
    asm("cvt.rna.tf32.f32 %0, %1;" : "=r"(r) : "f"(x));
    return r;
}

// ---------------- init ----------------
__global__ void k_zero_state() {
    int i = blockIdx.x * 256 + threadIdx.x;
    if (i < 2 * 2 * Bq * Hq) ((float*)g_henc)[i] = 0.f;
    if (i < 2 * Bq * Hq)     ((float*)g_cenc)[i] = 0.f;
}

__global__ void k_gather_src(const int* __restrict__ src, const float* __restrict__ emb) {
    int m = blockIdx.x;            // m = s*B + b
    int s = m / Bq, b = m % Bq;
    int idx = src[b * Sq + s];
    float4 v = ((const float4*)(emb + (size_t)idx * Eq))[threadIdx.x];
    ((float4*)(g_xsrc + (size_t)m * Eq))[threadIdx.x] = v;
}

__global__ void k_gather_tgt(const int* __restrict__ tgt, const float* __restrict__ emb) {
    int m = blockIdx.x;            // m = b*T + t
    int b = m / Tq, t = m % Tq;
    int idx = tgt[m];
    float4 v = ((const float4*)(emb + (size_t)idx * Eq))[threadIdx.x];
    ((float4*)(&g_temb[b][t][0]))[threadIdx.x] = v;
    ((float4*)(g_temb_tb + ((size_t)t * Bq + b) * Eq))[threadIdx.x] = v;
}

// ---------------- tf32 tensor-core GEMM ----------------
// C[M,N] = act(A[M,K] @ W[N,K]^T + bias1 (+bias2))
// block tile 128x128, BK=16, 256 threads = 8 warps (2 M x 4 N), warp tile 64x32.
// grid: (M/128, N/128) -- bm fastest so consecutive blocks share the W tile (L2 reuse).
#define SSTR 20   // shared stride in floats; conflict-free for fragment pattern
__global__ void __launch_bounds__(256) k_mma(
    const float* __restrict__ A, int lda,
    const float* __restrict__ W, int ldw,
    const float* __restrict__ bias1, const float* __restrict__ bias2,
    float* __restrict__ C, int ldc,
    int M, int N, int K, int do_relu)
{
    __shared__ uint32_t As[128 * SSTR];
    __shared__ uint32_t Ws[128 * SSTR];
    int tid = threadIdx.x;
    int bm = blockIdx.x * 128, bn = blockIdx.y * 128;

    int warp = tid >> 5, lane = tid & 31;
    int wm = warp & 1, wn = warp >> 1;           // warp tile: rows wm*64, cols wn*32
    int grp = lane >> 2, qid = lane & 3;

    // loader mapping: 512 float4 per tile (A) : idx -> row=idx>>2, quad=idx&3
    int l_row = (tid * 2) >> 2;                  // rows for i=0 ; i=1 adds 128
    int l_q0 = (tid * 2) & 3;

    float acc[4][4][4];
#pragma unroll
    for (int i = 0; i < 4; i++)
#pragma unroll
        for (int j = 0; j < 4; j++)
#pragma unroll
            for (int r = 0; r < 4; r++) acc[i][j][r] = 0.f;

    for (int k0 = 0; k0 < K; k0 += 16) {
        // load A tile 128x16 and W tile 128x16, convert to tf32, store swizzle-free
#pragma unroll
        for (int i = 0; i < 2; i++) {
            int idx = tid * 2 + i;               // 0..511
            int row = idx >> 2, q = idx & 3;
            float4 av = *(const float4*)(A + (size_t)(bm + row) * lda + k0 + q * 4);
            float4 wv = *(const float4*)(W + (size_t)(bn + row) * ldw + k0 + q * 4);
            uint4 at = make_uint4(f2tf(av.x), f2tf(av.y), f2tf(av.z), f2tf(av.w));
            uint4 wt = make_uint4(f2tf(wv.x), f2tf(wv.y), f2tf(wv.z), f2tf(wv.w));
            *(uint4*)&As[row * SSTR + q * 4] = at;
            *(uint4*)&Ws[row * SSTR + q * 4] = wt;
        }
        __syncthreads();
#pragma unroll
        for (int kf = 0; kf < 2; kf++) {
            int kb = kf * 8;
            uint32_t a[4][4], b[4][2];
#pragma unroll
            for (int mf = 0; mf < 4; mf++) {
                int rb = (wm * 64 + mf * 16) * SSTR + kb;
                a[mf][0] = As[rb + grp * SSTR + qid];
                a[mf][1] = As[rb + (grp + 8) * SSTR + qid];
                a[mf][2] = As[rb + grp * SSTR + qid + 4];
                a[mf][3] = As[rb + (grp + 8) * SSTR + qid + 4];
            }
#pragma unroll
            for (int nf = 0; nf < 4; nf++) {
                int cb = (wn * 32 + nf * 8 + grp) * SSTR + kb;
                b[nf][0] = Ws[cb + qid];
                b[nf][1] = Ws[cb + qid + 4];
            }
#pragma unroll
            for (int mf = 0; mf < 4; mf++)
#pragma unroll
                for (int nf = 0; nf < 4; nf++) {
                    asm volatile(
                        "mma.sync.aligned.m16n8k8.row.col.f32.tf32.tf32.f32 "
                        "{%0,%1,%2,%3}, {%4,%5,%6,%7}, {%8,%9}, {%0,%1,%2,%3};\n"
                        : "+f"(acc[mf][nf][0]), "+f"(acc[mf][nf][1]),
                          "+f"(acc[mf][nf][2]), "+f"(acc[mf][nf][3])
                        : "r"(a[mf][0]), "r"(a[mf][1]), "r"(a[mf][2]), "r"(a[mf][3]),
                          "r"(b[nf][0]), "r"(b[nf][1]));
                }
        }
        __syncthreads();
    }

    // epilogue
#pragma unroll
    for (int nf = 0; nf < 4; nf++) {
        int col = bn + wn * 32 + nf * 8 + qid * 2;
        float b0 = bias1[col], b1 = bias1[col + 1];
        if (bias2) { b0 += bias2[col]; b1 += bias2[col + 1]; }
#pragma unroll
        for (int mf = 0; mf < 4; mf++) {
            int row = bm + wm * 64 + mf * 16 + grp;
            float v0 = acc[mf][nf][0] + b0, v1 = acc[mf][nf][1] + b1;
            float v2 = acc[mf][nf][2] + b0, v3 = acc[mf][nf][3] + b1;
            if (do_relu) {
                v0 = fmaxf(v0, 0.f); v1 = fmaxf(v1, 0.f);
                v2 = fmaxf(v2, 0.f); v3 = fmaxf(v3, 0.f);
            }
            *(float2*)&C[(size_t)row * ldc + col] = make_float2(v0, v1);
            *(float2*)&C[(size_t)(row + 8) * ldc + col] = make_float2(v2, v3);
        }
    }
}

// ---------------- fused encoder step (both directions) ----------------
__global__ void __launch_bounds__(128) k_enc_step(int s,
    const float* __restrict__ Whh_f, const float* __restrict__ Whh_b)
{
    __shared__ float hs[Hq];
    __shared__ float gv[128];
    int chunk = blockIdx.x, b = blockIdx.y, d = blockIdx.z;
    int tid = threadIdx.x;
    int slot = s & 1;
    ((float4*)hs)[tid] = ((const float4*)&g_henc[slot][d][b][0])[tid];
    __syncthreads();
    int gate = tid >> 5, lane = tid & 31;
    int unit = chunk * 32 + lane;
    int grow = gate * Hq + unit;
    int seff = d ? (Sq - 1 - s) : s;
    const float* X = d ? g_Xb : g_Xf;
    const float* W = (d ? Whh_b : Whh_f) + (size_t)grow * Hq;
    float acc = X[((size_t)seff * Bq + b) * G4 + grow];
    const float4* W4 = (const float4*)W;
    const float4* h4 = (const float4*)hs;
#pragma unroll 8
    for (int k = 0; k < 128; k++) {
        float4 w = W4[k], h = h4[k];
        acc += w.x * h.x + w.y * h.y + w.z * h.z + w.w * h.w;
    }
    gv[tid] = acc;
    __syncthreads();
    if (tid < 32) {
        int u = chunk * 32 + tid;
        float iv = sigf(gv[tid]);
        float fv = sigf(gv[32 + tid]);
        float gg = tanhf(gv[64 + tid]);
        float ov = sigf(gv[96 + tid]);
        float c = g_cenc[d][b][u];
        c = fv * c + iv * gg;
        float h = ov * tanhf(c);
        g_cenc[d][b][u] = c;
        g_henc[slot ^ 1][d][b][u] = h;
        g_encout[b][seff][d * Hq + u] = h;
        g_encT[b][d * Hq + u][seff] = h;
    }
}

__global__ void k_dec_init() {
    int i = blockIdx.x * 256 + threadIdx.x;
    if (i < Bq * Hq) {
        ((float*)g_hdec)[i] = ((const float*)g_henc)[i];  // slot0, dir0 = final fwd h
        ((float*)g_cdec)[i] = ((const float*)g_cenc)[i];  // dir0 = final fwd c
    }
}

// ---------------- decoder: Q projection, k-split ----------------
__global__ void __launch_bounds__(256) k_qproj(int t, const float* __restrict__ att1_W) {
    __shared__ float hs[32][33];
    int tid = threadIdx.x;
    int jc = blockIdx.x, ks = blockIdx.y;
    int k0 = ks * 32;
    int slot = t & 1;
    {
        int b = tid >> 3, kk = (tid & 7) * 4;
        float4 v = *(const float4*)&g_hdec[slot][b][k0 + kk];
        hs[b][kk] = v.x; hs[b][kk + 1] = v.y; hs[b][kk + 2] = v.z; hs[b][kk + 3] = v.w;
    }
    __syncthreads();
    int j = jc * 128 + (tid & 127);
    int b0 = (tid >> 7) * 16;
    const float4* Wr = (const float4*)(att1_W + (size_t)j * H3 + H2 + k0);
    float acc[16];
#pragma unroll
    for (int b = 0; b < 16; b++) acc[b] = 0.f;
#pragma unroll
    for (int kg = 0; kg < 8; kg++) {
        float4 w = Wr[kg];
#pragma unroll
        for (int b = 0; b < 16; b++) {
            acc[b] += w.x * hs[b0 + b][kg * 4] + w.y * hs[b0 + b][kg * 4 + 1]
                    + w.z * hs[b0 + b][kg * 4 + 2] + w.w * hs[b0 + b][kg * 4 + 3];
        }
    }
#pragma unroll
    for (int b = 0; b < 16; b++) g_Qpart[ks][b0 + b][j] = acc[b];
}

// ---------------- decoder: scores + softmax + context ----------------
__global__ void __launch_bounds__(512) k_attn(int t, const float* __restrict__ att2_W) {
    __shared__ float Qs[H3];
    __shared__ float a2[H3];
    __shared__ float wsm[128];
    int b = blockIdx.x, tid = threadIdx.x;
    for (int j = tid; j < H3; j += 512) {
        a2[j] = att2_W[j];
        float q = 0.f;
#pragma unroll
        for (int p = 0; p < 16; p++) q += g_Qpart[p][b][j];
        Qs[j] = q;
    }
    __syncthreads();
    int warp = tid >> 5, lane = tid & 31;
    for (int s = warp; s < Sq; s += 16) {
        const float* Pp = g_P + ((size_t)b * Sq + s) * H3;
        float acc = 0.f;
        for (int j = lane; j < H3; j += 32) {
            float v = Pp[j] + Qs[j];
            acc += fmaxf(v, 0.f) * a2[j];
        }
#pragma unroll
        for (int o = 16; o; o >>= 1) acc += __shfl_xor_sync(0xffffffffu, acc, o);
        if (!lane) wsm[s] = acc;
    }
    __syncthreads();
    if (tid < 32) {
        float m = -1e30f;
        for (int s = tid; s < Sq; s += 32) m = fmaxf(m, wsm[s]);
#pragma unroll
        for (int o = 16; o; o >>= 1) m = fmaxf(m, __shfl_xor_sync(0xffffffffu, m, o));
        float e[4];
        float sum = 0.f;
        int i = 0;
        for (int s = tid; s < Sq; s += 32, i++) { e[i] = __expf(wsm[s] - m); sum += e[i]; }
#pragma unroll
        for (int o = 16; o; o >>= 1) sum += __shfl_xor_sync(0xffffffffu, sum, o);
        float inv = 1.f / sum;
        i = 0;
        for (int s = tid; s < Sq; s += 32, i++) wsm[s] = e[i] * inv;
    }
    __syncthreads();
    for (int k = tid; k < H2; k += 512) {
        const float* eT = &g_encT[b][k][0];
        float acc = 0.f;
#pragma unroll 4
        for (int s = 0; s < Sq; s++) acc += wsm[s] * eT[s];
        g_ctxs[t][b][k] = acc;
    }
}

// ---------------- decoder: fused LSTM gates + state update ----------------
__global__ void __launch_bounds__(128) k_dec_lstm(int t,
    const float* __restrict__ Wih, const float* __restrict__ Whh)
{
    __shared__ float xs[H2 + Hq];   // ctx (1024) then h (512)
    __shared__ float gv[128];
    int chunk = blockIdx.x, b = blockIdx.y, tid = threadIdx.x;
    int slot = t & 1;
    {
        const float4* c4 = (const float4*)&g_ctxs[t][b][0];
        float4* s4 = (float4*)xs;
        s4[tid] = c4[tid];
        s4[128 + tid] = c4[128 + tid];
        s4[256 + tid] = ((const float4*)&g_hdec[slot][b][0])[tid];
    }
    __syncthreads();
    int gate = tid >> 5, lane = tid & 31;
    int unit = chunk * 32 + lane;
    int grow = gate * Hq + unit;
    float acc = g_Xdec[((size_t)t * Bq + b) * G4 + grow];
    const float4* Wi4 = (const float4*)(Wih + (size_t)grow * H3 + Eq);
    const float4* x4 = (const float4*)xs;
#pragma unroll 8
    for (int k = 0; k < 256; k++) {
        float4 w = Wi4[k], x = x4[k];
        acc += w.x * x.x + w.y * x.y + w.z * x.z + w.w * x.w;
    }
    const float4* Wh4 = (const float4*)(Whh + (size_t)grow * Hq);
#pragma unroll 8
    for (int k = 0; k < 128; k++) {
        float4 w = Wh4[k], x = x4[256 + k];
        acc += w.x * x.x + w.y * x.y + w.z * x.z + w.w * x.w;
    }
    gv[tid] = acc;
    __syncthreads();
    if (tid < 32) {
        int u = chunk * 32 + tid;
        float iv = sigf(gv[tid]);
        float fv = sigf(gv[32 + tid]);
        float gg = tanhf(gv[64 + tid]);
        float ov = sigf(gv[96 + tid]);
        float c = g_cdec[b][u];
        c = fv * c + iv * gg;
        float h = ov * tanhf(c);
        g_cdec[b][u] = c;
        g_hdec[slot ^ 1][b][u] = h;
        g_decs[t][b][u] = h;
    }
}

// ---------------- classifier input pack ----------------
__global__ void k_pack() {
    int m = blockIdx.x;            // m = b*T + t
    int b = m / Tq, t = m % Tq;
    int tid = threadIdx.x;         // 128
    float4* dst = (float4*)(g_clsin + (size_t)m * 2048);
    dst[tid]       = ((const float4*)&g_temb[b][t][0])[tid];
    dst[128 + tid] = ((const float4*)&g_ctxs[t][b][0])[tid];
    dst[256 + tid] = ((const float4*)&g_ctxs[t][b][0])[128 + tid];
    dst[384 + tid] = ((const float4*)&g_decs[t][b][0])[tid];
}

// ---------------- host ----------------
extern "C" void kernel_launch(void* const* d_in, const int* in_sizes, int n_in,
                              void* d_out, int out_size) {
    (void)in_sizes; (void)n_in; (void)out_size;
    const int*   src       = (const int*)d_in[0];
    const int*   tgt       = (const int*)d_in[1];
    const float* src_emb   = (const float*)d_in[2];
    const float* tgt_emb   = (const float*)d_in[3];
    const float* eWih_f    = (const float*)d_in[4];
    const float* eWhh_f    = (const float*)d_in[5];
    const float* ebih_f    = (const float*)d_in[6];
    const float* ebhh_f    = (const float*)d_in[7];
    const float* eWih_b    = (const float*)d_in[8];
    const float* eWhh_b    = (const float*)d_in[9];
    const float* ebih_b    = (const float*)d_in[10];
    const float* ebhh_b    = (const float*)d_in[11];
    const float* dWih      = (const float*)d_in[12];
    const float* dWhh      = (const float*)d_in[13];
    const float* dbih      = (const float*)d_in[14];
    const float* dbhh      = (const float*)d_in[15];
    const float* att1_W    = (const float*)d_in[16];
    const float* att1_b    = (const float*)d_in[17];
    const float* att2_W    = (const float*)d_in[18];
    const float* cls1_W    = (const float*)d_in[20];
    const float* cls1_b    = (const float*)d_in[21];
    const float* cls2_W    = (const float*)d_in[22];
    const float* cls2_b    = (const float*)d_in[23];
    float* out = (float*)d_out;

    float *p_xsrc, *p_Xf, *p_Xb, *p_encout, *p_P, *p_temb_tb, *p_Xdec, *p_clsin, *p_hid;
    cudaGetSymbolAddress((void**)&p_xsrc, g_xsrc);
    cudaGetSymbolAddress((void**)&p_Xf, g_Xf);
    cudaGetSymbolAddress((void**)&p_Xb, g_Xb);
    cudaGetSymbolAddress((void**)&p_encout, g_encout);
    cudaGetSymbolAddress((void**)&p_P, g_P);
    cudaGetSymbolAddress((void**)&p_temb_tb, g_temb_tb);
    cudaGetSymbolAddress((void**)&p_Xdec, g_Xdec);
    cudaGetSymbolAddress((void**)&p_clsin, g_clsin);
    cudaGetSymbolAddress((void**)&p_hid, g_hid);

    k_zero_state<<<256, 256>>>();
    k_gather_src<<<Sq * Bq, 128>>>(src, src_emb);
    k_gather_tgt<<<Bq * Tq, 128>>>(tgt, tgt_emb);

    // encoder input gate precompute: [3200,512] x [2048,512]^T
    k_mma<<<dim3(25, 16), 256>>>(p_xsrc, Eq, eWih_f, Eq, ebih_f, ebhh_f,
                                 p_Xf, G4, Sq * Bq, G4, Eq, 0);
    k_mma<<<dim3(25, 16), 256>>>(p_xsrc, Eq, eWih_b, Eq, ebih_b, ebhh_b,
                                 p_Xb, G4, Sq * Bq, G4, Eq, 0);

    for (int s = 0; s < Sq; s++)
        k_enc_step<<<dim3(16, 32, 2), 128>>>(s, eWhh_f, eWhh_b);

    // attention layer-1 enc part, hoisted: [3200,1024] x [1536 rows, first 1024 cols]^T
    k_mma<<<dim3(25, 12), 256>>>(p_encout, H2, att1_W, H3, att1_b, (const float*)nullptr,
                                 p_P, H3, Bq * Sq, H3, H2, 0);

    // decoder input gate precompute (embedding part)
    k_mma<<<dim3(25, 16), 256>>>(p_temb_tb, Eq, dWih, H3, dbih, dbhh,
                                 p_Xdec, G4, Tq * Bq, G4, Eq, 0);

    k_dec_init<<<64, 256>>>();

    for (int t = 0; t < Tq; t++) {
        k_qproj<<<dim3(12, 16), 256>>>(t, att1_W);
        k_attn<<<32, 512>>>(t, att2_W);
        k_dec_lstm<<<dim3(16, 32), 128>>>(t, dWih, dWhh);
    }

    k_pack<<<Bq * Tq, 128>>>();

    // classifier
    k_mma<<<dim3(25, 8), 256>>>(p_clsin, 2048, cls1_W, 2048, cls1_b, (const float*)nullptr,
                                p_hid, H2, Bq * Tq, H2, 2048, 1);
    k_mma<<<dim3(25, 250), 256>>>(p_hid, H2, cls2_W, H2, cls2_b, (const float*)nullptr,
                                  out, VTq, Bq * Tq, VTq, H2, 0);
}

// round 8
// speedup vs baseline: 1.0005x; 1.0005x over previous
#include <cuda_runtime.h>
#include <cstdint>
#include <cstddef>

#define Bq 32
#define Sq 100
#define Tq 100
#define Eq 512
#define Hq 512
#define G4 2048   // 4H
#define H2 1024   // 2H
#define H3 1536   // 3H
#define VTq 32000

// ---------------- scratch (static device globals; no allocation) ----------------
__device__ float g_xsrc[Sq * Bq * Eq];            // gathered source embeddings [S,B,E]
__device__ float g_Xf[Sq * Bq * G4];              // fwd enc input gates [S,B,4H]
__device__ float g_Xb[Sq * Bq * G4];              // bwd enc input gates [S,B,4H]
__device__ float g_henc[2][2][Bq][Hq];            // [slot][dir][b][h] ping-pong
__device__ float g_cenc[2][Bq][Hq];               // [dir][b][h]
__device__ float g_encout[Bq][Sq][H2];            // [B,S,2H]
__device__ float g_encT[Bq][H2][Sq];              // transposed for ctx reduction
__device__ float g_P[(size_t)Bq * Sq * H3];       // precomputed att layer1 (enc part)
__device__ float g_temb[Bq][Tq][Eq];
__device__ float g_temb_tb[Tq * Bq * Eq];         // [T,B,E]
__device__ float g_Xdec[Tq * Bq * G4];            // dec input gates (emb part) [T,B,4H]
__device__ float g_hdec[2][Bq][Hq];
__device__ float g_cdec[Bq][Hq];
__device__ float g_Qpart[16][Bq][H3];             // k-split partials of Q projection
__device__ float g_ctxs[Tq][Bq][H2];
__device__ float g_decs[Tq][Bq][Hq];
__device__ float g_clsin[(size_t)Bq * Tq * 2048];
__device__ float g_hid[(size_t)Bq * Tq * H2];

__device__ __forceinline__ float sigf(float x) { return 1.f / (1.f + __expf(-x)); }

__device__ __forceinline__ uint32_t f2tf(float x) {
    uint32_t r;
    asm("cvt.rna.tf32.f32 %0, %1;" : "=r"(r) : "f"(x));
    return r;
}

// ---------------- init ----------------
__global__ void k_zero_state() {
    int i = blockIdx.x * 256 + threadIdx.x;
    if (i < 2 * 2 * Bq * Hq) ((float*)g_henc)[i] = 0.f;
    if (i < 2 * Bq * Hq)     ((float*)g_cenc)[i] = 0.f;
}

__global__ void k_gather_src(const int* __restrict__ src, const float* __restrict__ emb) {
    int m = blockIdx.x;            // m = s*B + b
    int s = m / Bq, b = m % Bq;
    int idx = src[b * Sq + s];
    float4 v = ((const float4*)(emb + (size_t)idx * Eq))[threadIdx.x];
    ((float4*)(g_xsrc + (size_t)m * Eq))[threadIdx.x] = v;
}

__global__ void k_gather_tgt(const int* __restrict__ tgt, const float* __restrict__ emb) {
    int m = blockIdx.x;            // m = b*T + t
    int b = m / Tq, t = m % Tq;
    int idx = tgt[m];
    float4 v = ((const float4*)(emb + (size_t)idx * Eq))[threadIdx.x];
    ((float4*)(&g_temb[b][t][0]))[threadIdx.x] = v;
    ((float4*)(g_temb_tb + ((size_t)t * Bq + b) * Eq))[threadIdx.x] = v;
}

// ---------------- tf32 tensor-core GEMM ----------------
// C[M,N] = act(A[M,K] @ W[N,K]^T + bias1 (+bias2))
// block tile 128x128, BK=16, 256 threads = 8 warps (2 M x 4 N), warp tile 64x32.
// grid: (M/128, N/128) -- bm fastest so consecutive blocks share the W tile (L2 reuse).
#define SSTR 20   // shared stride in floats; conflict-free for fragment pattern
__global__ void __launch_bounds__(256) k_mma(
    const float* __restrict__ A, int lda,
    const float* __restrict__ W, int ldw,
    const float* __restrict__ bias1, const float* __restrict__ bias2,
    float* __restrict__ C, int ldc,
    int M, int N, int K, int do_relu)
{
    __shared__ uint32_t As[128 * SSTR];
    __shared__ uint32_t Ws[128 * SSTR];
    int tid = threadIdx.x;
    int bm = blockIdx.x * 128, bn = blockIdx.y * 128;

    int warp = tid >> 5, lane = tid & 31;
    int wm = warp & 1, wn = warp >> 1;           // warp tile: rows wm*64, cols wn*32
    int grp = lane >> 2, qid = lane & 3;

    // loader mapping: 512 float4 per tile (A) : idx -> row=idx>>2, quad=idx&3
    int l_row = (tid * 2) >> 2;                  // rows for i=0 ; i=1 adds 128
    int l_q0 = (tid * 2) & 3;

    float acc[4][4][4];
#pragma unroll
    for (int i = 0; i < 4; i++)
#pragma unroll
        for (int j = 0; j < 4; j++)
#pragma unroll
            for (int r = 0; r < 4; r++) acc[i][j][r] = 0.f;

    for (int k0 = 0; k0 < K; k0 += 16) {
        // load A tile 128x16 and W tile 128x16, convert to tf32, store swizzle-free
#pragma unroll
        for (int i = 0; i < 2; i++) {
            int idx = tid * 2 + i;               // 0..511
            int row = idx >> 2, q = idx & 3;
            float4 av = *(const float4*)(A + (size_t)(bm + row) * lda + k0 + q * 4);
            float4 wv = *(const float4*)(W + (size_t)(bn + row) * ldw + k0 + q * 4);
            uint4 at = make_uint4(f2tf(av.x), f2tf(av.y), f2tf(av.z), f2tf(av.w));
            uint4 wt = make_uint4(f2tf(wv.x), f2tf(wv.y), f2tf(wv.z), f2tf(wv.w));
            *(uint4*)&As[row * SSTR + q * 4] = at;
            *(uint4*)&Ws[row * SSTR + q * 4] = wt;
        }
        __syncthreads();
#pragma unroll
        for (int kf = 0; kf < 2; kf++) {
            int kb = kf * 8;
            uint32_t a[4][4], b[4][2];
#pragma unroll
            for (int mf = 0; mf < 4; mf++) {
                int rb = (wm * 64 + mf * 16) * SSTR + kb;
                a[mf][0] = As[rb + grp * SSTR + qid];
                a[mf][1] = As[rb + (grp + 8) * SSTR + qid];
                a[mf][2] = As[rb + grp * SSTR + qid + 4];
                a[mf][3] = As[rb + (grp + 8) * SSTR + qid + 4];
            }
#pragma unroll
            for (int nf = 0; nf < 4; nf++) {
                int cb = (wn * 32 + nf * 8 + grp) * SSTR + kb;
                b[nf][0] = Ws[cb + qid];
                b[nf][1] = Ws[cb + qid + 4];
            }
#pragma unroll
            for (int mf = 0; mf < 4; mf++)
#pragma unroll
                for (int nf = 0; nf < 4; nf++) {
                    asm volatile(
                        "mma.sync.aligned.m16n8k8.row.col.f32.tf32.tf32.f32 "
                        "{%0,%1,%2,%3}, {%4,%5,%6,%7}, {%8,%9}, {%0,%1,%2,%3};\n"
                        : "+f"(acc[mf][nf][0]), "+f"(acc[mf][nf][1]),
                          "+f"(acc[mf][nf][2]), "+f"(acc[mf][nf][3])
                        : "r"(a[mf][0]), "r"(a[mf][1]), "r"(a[mf][2]), "r"(a[mf][3]),
                          "r"(b[nf][0]), "r"(b[nf][1]));
                }
        }
        __syncthreads();
    }

    // epilogue
#pragma unroll
    for (int nf = 0; nf < 4; nf++) {
        int col = bn + wn * 32 + nf * 8 + qid * 2;
        float b0 = bias1[col], b1 = bias1[col + 1];
        if (bias2) { b0 += bias2[col]; b1 += bias2[col + 1]; }
#pragma unroll
        for (int mf = 0; mf < 4; mf++) {
            int row = bm + wm * 64 + mf * 16 + grp;
            float v0 = acc[mf][nf][0] + b0, v1 = acc[mf][nf][1] + b1;
            float v2 = acc[mf][nf][2] + b0, v3 = acc[mf][nf][3] + b1;
            if (do_relu) {
                v0 = fmaxf(v0, 0.f); v1 = fmaxf(v1, 0.f);
                v2 = fmaxf(v2, 0.f); v3 = fmaxf(v3, 0.f);
            }
            *(float2*)&C[(size_t)row * ldc + col] = make_float2(v0, v1);
            *(float2*)&C[(size_t)(row + 8) * ldc + col] = make_float2(v2, v3);
        }
    }
}

// ---------------- fused encoder step (both directions) ----------------
__global__ void __launch_bounds__(128) k_enc_step(int s,
    const float* __restrict__ Whh_f, const float* __restrict__ Whh_b)
{
    __shared__ float hs[Hq];
    __shared__ float gv[128];
    int chunk = blockIdx.x, b = blockIdx.y, d = blockIdx.z;
    int tid = threadIdx.x;
    int slot = s & 1;
    ((float4*)hs)[tid] = ((const float4*)&g_henc[slot][d][b][0])[tid];
    __syncthreads();
    int gate = tid >> 5, lane = tid & 31;
    int unit = chunk * 32 + lane;
    int grow = gate * Hq + unit;
    int seff = d ? (Sq - 1 - s) : s;
    const float* X = d ? g_Xb : g_Xf;
    const float* W = (d ? Whh_b : Whh_f) + (size_t)grow * Hq;
    float acc = X[((size_t)seff * Bq + b) * G4 + grow];
    const float4* W4 = (const float4*)W;
    const float4* h4 = (const float4*)hs;
#pragma unroll 8
    for (int k = 0; k < 128; k++) {
        float4 w = W4[k], h = h4[k];
        acc += w.x * h.x + w.y * h.y + w.z * h.z + w.w * h.w;
    }
    gv[tid] = acc;
    __syncthreads();
    if (tid < 32) {
        int u = chunk * 32 + tid;
        float iv = sigf(gv[tid]);
        float fv = sigf(gv[32 + tid]);
        float gg = tanhf(gv[64 + tid]);
        float ov = sigf(gv[96 + tid]);
        float c = g_cenc[d][b][u];
        c = fv * c + iv * gg;
        float h = ov * tanhf(c);
        g_cenc[d][b][u] = c;
        g_henc[slot ^ 1][d][b][u] = h;
        g_encout[b][seff][d * Hq + u] = h;
        g_encT[b][d * Hq + u][seff] = h;
    }
}

__global__ void k_dec_init() {
    int i = blockIdx.x * 256 + threadIdx.x;
    if (i < Bq * Hq) {
        ((float*)g_hdec)[i] = ((const float*)g_henc)[i];  // slot0, dir0 = final fwd h
        ((float*)g_cdec)[i] = ((const float*)g_cenc)[i];  // dir0 = final fwd c
    }
}

// ---------------- decoder: Q projection, k-split ----------------
__global__ void __launch_bounds__(256) k_qproj(int t, const float* __restrict__ att1_W) {
    __shared__ float hs[32][33];
    int tid = threadIdx.x;
    int jc = blockIdx.x, ks = blockIdx.y;
    int k0 = ks * 32;
    int slot = t & 1;
    {
        int b = tid >> 3, kk = (tid & 7) * 4;
        float4 v = *(const float4*)&g_hdec[slot][b][k0 + kk];
        hs[b][kk] = v.x; hs[b][kk + 1] = v.y; hs[b][kk + 2] = v.z; hs[b][kk + 3] = v.w;
    }
    __syncthreads();
    int j = jc * 128 + (tid & 127);
    int b0 = (tid >> 7) * 16;
    const float4* Wr = (const float4*)(att1_W + (size_t)j * H3 + H2 + k0);
    float acc[16];
#pragma unroll
    for (int b = 0; b < 16; b++) acc[b] = 0.f;
#pragma unroll
    for (int kg = 0; kg < 8; kg++) {
        float4 w = Wr[kg];
#pragma unroll
        for (int b = 0; b < 16; b++) {
            acc[b] += w.x * hs[b0 + b][kg * 4] + w.y * hs[b0 + b][kg * 4 + 1]
                    + w.z * hs[b0 + b][kg * 4 + 2] + w.w * hs[b0 + b][kg * 4 + 3];
        }
    }
#pragma unroll
    for (int b = 0; b < 16; b++) g_Qpart[ks][b0 + b][j] = acc[b];
}

// ---------------- decoder: scores + softmax + context ----------------
__global__ void __launch_bounds__(512) k_attn(int t, const float* __restrict__ att2_W) {
    __shared__ float Qs[H3];
    __shared__ float a2[H3];
    __shared__ float wsm[128];
    int b = blockIdx.x, tid = threadIdx.x;
    for (int j = tid; j < H3; j += 512) {
        a2[j] = att2_W[j];
        float q = 0.f;
#pragma unroll
        for (int p = 0; p < 16; p++) q += g_Qpart[p][b][j];
        Qs[j] = q;
    }
    __syncthreads();
    int warp = tid >> 5, lane = tid & 31;
    for (int s = warp; s < Sq; s += 16) {
        const float* Pp = g_P + ((size_t)b * Sq + s) * H3;
        float acc = 0.f;
        for (int j = lane; j < H3; j += 32) {
            float v = Pp[j] + Qs[j];
            acc += fmaxf(v, 0.f) * a2[j];
        }
#pragma unroll
        for (int o = 16; o; o >>= 1) acc += __shfl_xor_sync(0xffffffffu, acc, o);
        if (!lane) wsm[s] = acc;
    }
    __syncthreads();
    if (tid < 32) {
        float m = -1e30f;
        for (int s = tid; s < Sq; s += 32) m = fmaxf(m, wsm[s]);
#pragma unroll
        for (int o = 16; o; o >>= 1) m = fmaxf(m, __shfl_xor_sync(0xffffffffu, m, o));
        float e[4];
        float sum = 0.f;
        int i = 0;
        for (int s = tid; s < Sq; s += 32, i++) { e[i] = __expf(wsm[s] - m); sum += e[i]; }
#pragma unroll
        for (int o = 16; o; o >>= 1) sum += __shfl_xor_sync(0xffffffffu, sum, o);
        float inv = 1.f / sum;
        i = 0;
        for (int s = tid; s < Sq; s += 32, i++) wsm[s] = e[i] * inv;
    }
    __syncthreads();
    for (int k = tid; k < H2; k += 512) {
        const float* eT = &g_encT[b][k][0];
        float acc = 0.f;
#pragma unroll 4
        for (int s = 0; s < Sq; s++) acc += wsm[s] * eT[s];
        g_ctxs[t][b][k] = acc;
    }
}

// ---------------- decoder: fused LSTM gates + state update ----------------
__global__ void __launch_bounds__(128) k_dec_lstm(int t,
    const float* __restrict__ Wih, const float* __restrict__ Whh)
{
    __shared__ float xs[H2 + Hq];   // ctx (1024) then h (512)
    __shared__ float gv[128];
    int chunk = blockIdx.x, b = blockIdx.y, tid = threadIdx.x;
    int slot = t & 1;
    {
        const float4* c4 = (const float4*)&g_ctxs[t][b][0];
        float4* s4 = (float4*)xs;
        s4[tid] = c4[tid];
        s4[128 + tid] = c4[128 + tid];
        s4[256 + tid] = ((const float4*)&g_hdec[slot][b][0])[tid];
    }
    __syncthreads();
    int gate = tid >> 5, lane = tid & 31;
    int unit = chunk * 32 + lane;
    int grow = gate * Hq + unit;
    float acc = g_Xdec[((size_t)t * Bq + b) * G4 + grow];
    const float4* Wi4 = (const float4*)(Wih + (size_t)grow * H3 + Eq);
    const float4* x4 = (const float4*)xs;
#pragma unroll 8
    for (int k = 0; k < 256; k++) {
        float4 w = Wi4[k], x = x4[k];
        acc += w.x * x.x + w.y * x.y + w.z * x.z + w.w * x.w;
    }
    const float4* Wh4 = (const float4*)(Whh + (size_t)grow * Hq);
#pragma unroll 8
    for (int k = 0; k < 128; k++) {
        float4 w = Wh4[k], x = x4[256 + k];
        acc += w.x * x.x + w.y * x.y + w.z * x.z + w.w * x.w;
    }
    gv[tid] = acc;
    __syncthreads();
    if (tid < 32) {
        int u = chunk * 32 + tid;
        float iv = sigf(gv[tid]);
        float fv = sigf(gv[32 + tid]);
        float gg = tanhf(gv[64 + tid]);
        float ov = sigf(gv[96 + tid]);
        float c = g_cdec[b][u];
        c = fv * c + iv * gg;
        float h = ov * tanhf(c);
        g_cdec[b][u] = c;
        g_hdec[slot ^ 1][b][u] = h;
        g_decs[t][b][u] = h;
    }
}

// ---------------- classifier input pack ----------------
__global__ void k_pack() {
    int m = blockIdx.x;            // m = b*T + t
    int b = m / Tq, t = m % Tq;
    int tid = threadIdx.x;         // 128
    float4* dst = (float4*)(g_clsin + (size_t)m * 2048);
    dst[tid]       = ((const float4*)&g_temb[b][t][0])[tid];
    dst[128 + tid] = ((const float4*)&g_ctxs[t][b][0])[tid];
    dst[256 + tid] = ((const float4*)&g_ctxs[t][b][0])[128 + tid];
    dst[384 + tid] = ((const float4*)&g_decs[t][b][0])[tid];
}

// ---------------- host ----------------
extern "C" void kernel_launch(void* const* d_in, const int* in_sizes, int n_in,
                              void* d_out, int out_size) {
    (void)in_sizes; (void)n_in; (void)out_size;
    const int*   src       = (const int*)d_in[0];
    const int*   tgt       = (const int*)d_in[1];
    const float* src_emb   = (const float*)d_in[2];
    const float* tgt_emb   = (const float*)d_in[3];
    const float* eWih_f    = (const float*)d_in[4];
    const float* eWhh_f    = (const float*)d_in[5];
    const float* ebih_f    = (const float*)d_in[6];
    const float* ebhh_f    = (const float*)d_in[7];
    const float* eWih_b    = (const float*)d_in[8];
    const float* eWhh_b    = (const float*)d_in[9];
    const float* ebih_b    = (const float*)d_in[10];
    const float* ebhh_b    = (const float*)d_in[11];
    const float* dWih      = (const float*)d_in[12];
    const float* dWhh      = (const float*)d_in[13];
    const float* dbih      = (const float*)d_in[14];
    const float* dbhh      = (const float*)d_in[15];
    const float* att1_W    = (const float*)d_in[16];
    const float* att1_b    = (const float*)d_in[17];
    const float* att2_W    = (const float*)d_in[18];
    const float* cls1_W    = (const float*)d_in[20];
    const float* cls1_b    = (const float*)d_in[21];
    const float* cls2_W    = (const float*)d_in[22];
    const float* cls2_b    = (const float*)d_in[23];
    float* out = (float*)d_out;

    float *p_xsrc, *p_Xf, *p_Xb, *p_encout, *p_P, *p_temb_tb, *p_Xdec, *p_clsin, *p_hid;
    cudaGetSymbolAddress((void**)&p_xsrc, g_xsrc);
    cudaGetSymbolAddress((void**)&p_Xf, g_Xf);
    cudaGetSymbolAddress((void**)&p_Xb, g_Xb);
    cudaGetSymbolAddress((void**)&p_encout, g_encout);
    cudaGetSymbolAddress((void**)&p_P, g_P);
    cudaGetSymbolAddress((void**)&p_temb_tb, g_temb_tb);
    cudaGetSymbolAddress((void**)&p_Xdec, g_Xdec);
    cudaGetSymbolAddress((void**)&p_clsin, g_clsin);
    cudaGetSymbolAddress((void**)&p_hid, g_hid);

    k_zero_state<<<256, 256>>>();
    k_gather_src<<<Sq * Bq, 128>>>(src, src_emb);
    k_gather_tgt<<<Bq * Tq, 128>>>(tgt, tgt_emb);

    // encoder input gate precompute: [3200,512] x [2048,512]^T
    k_mma<<<dim3(25, 16), 256>>>(p_xsrc, Eq, eWih_f, Eq, ebih_f, ebhh_f,
                                 p_Xf, G4, Sq * Bq, G4, Eq, 0);
    k_mma<<<dim3(25, 16), 256>>>(p_xsrc, Eq, eWih_b, Eq, ebih_b, ebhh_b,
                                 p_Xb, G4, Sq * Bq, G4, Eq, 0);

    for (int s = 0; s < Sq; s++)
        k_enc_step<<<dim3(16, 32, 2), 128>>>(s, eWhh_f, eWhh_b);

    // attention layer-1 enc part, hoisted: [3200,1024] x [1536 rows, first 1024 cols]^T
    k_mma<<<dim3(25, 12), 256>>>(p_encout, H2, att1_W, H3, att1_b, (const float*)nullptr,
                                 p_P, H3, Bq * Sq, H3, H2, 0);

    // decoder input gate precompute (embedding part)
    k_mma<<<dim3(25, 16), 256>>>(p_temb_tb, Eq, dWih, H3, dbih, dbhh,
                                 p_Xdec, G4, Tq * Bq, G4, Eq, 0);

    k_dec_init<<<64, 256>>>();

    for (int t = 0; t < Tq; t++) {
        k_qproj<<<dim3(12, 16), 256>>>(t, att1_W);
        k_attn<<<32, 512>>>(t, att2_W);
        k_dec_lstm<<<dim3(16, 32), 128>>>(t, dWih, dWhh);
    }

    k_pack<<<Bq * Tq, 128>>>();

    // classifier
    k_mma<<<dim3(25, 8), 256>>>(p_clsin, 2048, cls1_W, 2048, cls1_b, (const float*)nullptr,
                                p_hid, H2, Bq * Tq, H2, 2048, 1);
    k_mma<<<dim3(25, 250), 256>>>(p_hid, H2, cls2_W, H2, cls2_b, (const float*)nullptr,
                                  out, VTq, Bq * Tq, VTq, H2, 0);
}

// round 9
// speedup vs baseline: 1.0027x; 1.0022x over previous
#include <cuda_runtime.h>
#include <cstdint>
#include <cstddef>

#define Bq 32
#define Sq 100
#define Tq 100
#define Eq 512
#define Hq 512
#define G4 2048   // 4H
#define H2 1024   // 2H
#define H3 1536   // 3H
#define VTq 32000

// ---------------- scratch (static device globals; no allocation) ----------------
__device__ float g_xsrc[Sq * Bq * Eq];            // gathered source embeddings [S,B,E]
__device__ float g_Xf[Sq * Bq * G4];              // fwd enc input gates [S,B,4H]
__device__ float g_Xb[Sq * Bq * G4];              // bwd enc input gates [S,B,4H]
__device__ float g_henc[2][2][Bq][Hq];            // [slot][dir][b][h] ping-pong
__device__ float g_cenc[2][Bq][Hq];               // [dir][b][h]
__device__ float g_encout[Bq][Sq][H2];            // [B,S,2H]
__device__ float g_encT[Bq][H2][Sq];              // transposed for ctx reduction
__device__ float g_P[(size_t)Bq * Sq * H3];       // precomputed att layer1 (enc part)
__device__ float g_temb[Bq][Tq][Eq];
__device__ float g_temb_tb[Tq * Bq * Eq];         // [T,B,E]
__device__ float g_Xdec[Tq * Bq * G4];            // dec input gates (emb part) [T,B,4H]
__device__ float g_hdec[2][Bq][Hq];
__device__ float g_cdec[Bq][Hq];
__device__ float g_Qpart[16][Bq][H3];             // k-split partials of Q projection
__device__ float g_ctxs[Tq][Bq][H2];
__device__ float g_decs[Tq][Bq][Hq];
__device__ float g_clsin[(size_t)Bq * Tq * 2048];
__device__ float g_hid[(size_t)Bq * Tq * H2];

__device__ __forceinline__ float sigf(float x) { return 1.f / (1.f + __expf(-x)); }

__device__ __forceinline__ uint32_t f2tf(float x) {
    uint32_t r;
    asm("cvt.rna.tf32.f32 %0, %1;" : "=r"(r) : "f"(x));
    return r;
}

// ---------------- init ----------------
__global__ void k_zero_state() {
    int i = blockIdx.x * 256 + threadIdx.x;
    if (i < 2 * 2 * Bq * Hq) ((float*)g_henc)[i] = 0.f;
    if (i < 2 * Bq * Hq)     ((float*)g_cenc)[i] = 0.f;
}

__global__ void k_gather_src(const int* __restrict__ src, const float* __restrict__ emb) {
    int m = blockIdx.x;            // m = s*B + b
    int s = m / Bq, b = m % Bq;
    int idx = src[b * Sq + s];
    float4 v = ((const float4*)(emb + (size_t)idx * Eq))[threadIdx.x];
    ((float4*)(g_xsrc + (size_t)m * Eq))[threadIdx.x] = v;
}

__global__ void k_gather_tgt(const int* __restrict__ tgt, const float* __restrict__ emb) {
    int m = blockIdx.x;            // m = b*T + t
    int b = m / Tq, t = m % Tq;
    int idx = tgt[m];
    float4 v = ((const float4*)(emb + (size_t)idx * Eq))[threadIdx.x];
    ((float4*)(&g_temb[b][t][0]))[threadIdx.x] = v;
    ((float4*)(g_temb_tb + ((size_t)t * Bq + b) * Eq))[threadIdx.x] = v;
}

// ---------------- tf32 tensor-core GEMM ----------------
// C[M,N] = act(A[M,K] @ W[N,K]^T + bias1 (+bias2))
// block tile 128x128, BK=16, 256 threads = 8 warps (2 M x 4 N), warp tile 64x32.
// grid: (M/128, N/128) -- bm fastest so consecutive blocks share the W tile (L2 reuse).
#define SSTR 20   // shared stride in floats; conflict-free for fragment pattern
__global__ void __launch_bounds__(256) k_mma(
    const float* __restrict__ A, int lda,
    const float* __restrict__ W, int ldw,
    const float* __restrict__ bias1, const float* __restrict__ bias2,
    float* __restrict__ C, int ldc,
    int M, int N, int K, int do_relu)
{
    __shared__ uint32_t As[128 * SSTR];
    __shared__ uint32_t Ws[128 * SSTR];
    int tid = threadIdx.x;
    int bm = blockIdx.x * 128, bn = blockIdx.y * 128;

    int warp = tid >> 5, lane = tid & 31;
    int wm = warp & 1, wn = warp >> 1;           // warp tile: rows wm*64, cols wn*32
    int grp = lane >> 2, qid = lane & 3;

    // loader mapping: 512 float4 per tile (A) : idx -> row=idx>>2, quad=idx&3
    int l_row = (tid * 2) >> 2;                  // rows for i=0 ; i=1 adds 128
    int l_q0 = (tid * 2) & 3;

    float acc[4][4][4];
#pragma unroll
    for (int i = 0; i < 4; i++)
#pragma unroll
        for (int j = 0; j < 4; j++)
#pragma unroll
            for (int r = 0; r < 4; r++) acc[i][j][r] = 0.f;

    for (int k0 = 0; k0 < K; k0 += 16) {
        // load A tile 128x16 and W tile 128x16, convert to tf32, store swizzle-free
#pragma unroll
        for (int i = 0; i < 2; i++) {
            int idx = tid * 2 + i;               // 0..511
            int row = idx >> 2, q = idx & 3;
            float4 av = *(const float4*)(A + (size_t)(bm + row) * lda + k0 + q * 4);
            float4 wv = *(const float4*)(W + (size_t)(bn + row) * ldw + k0 + q * 4);
            uint4 at = make_uint4(f2tf(av.x), f2tf(av.y), f2tf(av.z), f2tf(av.w));
            uint4 wt = make_uint4(f2tf(wv.x), f2tf(wv.y), f2tf(wv.z), f2tf(wv.w));
            *(uint4*)&As[row * SSTR + q * 4] = at;
            *(uint4*)&Ws[row * SSTR + q * 4] = wt;
        }
        __syncthreads();
#pragma unroll
        for (int kf = 0; kf < 2; kf++) {
            int kb = kf * 8;
            uint32_t a[4][4], b[4][2];
#pragma unroll
            for (int mf = 0; mf < 4; mf++) {
                int rb = (wm * 64 + mf * 16) * SSTR + kb;
                a[mf][0] = As[rb + grp * SSTR + qid];
                a[mf][1] = As[rb + (grp + 8) * SSTR + qid];
                a[mf][2] = As[rb + grp * SSTR + qid + 4];
                a[mf][3] = As[rb + (grp + 8) * SSTR + qid + 4];
            }
#pragma unroll
            for (int nf = 0; nf < 4; nf++) {
                int cb = (wn * 32 + nf * 8 + grp) * SSTR + kb;
                b[nf][0] = Ws[cb + qid];
                b[nf][1] = Ws[cb + qid + 4];
            }
#pragma unroll
            for (int mf = 0; mf < 4; mf++)
#pragma unroll
                for (int nf = 0; nf < 4; nf++) {
                    asm volatile(
                        "mma.sync.aligned.m16n8k8.row.col.f32.tf32.tf32.f32 "
                        "{%0,%1,%2,%3}, {%4,%5,%6,%7}, {%8,%9}, {%0,%1,%2,%3};\n"
                        : "+f"(acc[mf][nf][0]), "+f"(acc[mf][nf][1]),
                          "+f"(acc[mf][nf][2]), "+f"(acc[mf][nf][3])
                        : "r"(a[mf][0]), "r"(a[mf][1]), "r"(a[mf][2]), "r"(a[mf][3]),
                          "r"(b[nf][0]), "r"(b[nf][1]));
                }
        }
        __syncthreads();
    }

    // epilogue
#pragma unroll
    for (int nf = 0; nf < 4; nf++) {
        int col = bn + wn * 32 + nf * 8 + qid * 2;
        float b0 = bias1[col], b1 = bias1[col + 1];
        if (bias2) { b0 += bias2[col]; b1 += bias2[col + 1]; }
#pragma unroll
        for (int mf = 0; mf < 4; mf++) {
            int row = bm + wm * 64 + mf * 16 + grp;
            float v0 = acc[mf][nf][0] + b0, v1 = acc[mf][nf][1] + b1;
            float v2 = acc[mf][nf][2] + b0, v3 = acc[mf][nf][3] + b1;
            if (do_relu) {
                v0 = fmaxf(v0, 0.f); v1 = fmaxf(v1, 0.f);
                v2 = fmaxf(v2, 0.f); v3 = fmaxf(v3, 0.f);
            }
            *(float2*)&C[(size_t)row * ldc + col] = make_float2(v0, v1);
            *(float2*)&C[(size_t)(row + 8) * ldc + col] = make_float2(v2, v3);
        }
    }
}

// ---------------- fused encoder step (both directions) ----------------
__global__ void __launch_bounds__(128) k_enc_step(int s,
    const float* __restrict__ Whh_f, const float* __restrict__ Whh_b)
{
    __shared__ float hs[Hq];
    __shared__ float gv[128];
    int chunk = blockIdx.x, b = blockIdx.y, d = blockIdx.z;
    int tid = threadIdx.x;
    int slot = s & 1;
    ((float4*)hs)[tid] = ((const float4*)&g_henc[slot][d][b][0])[tid];
    __syncthreads();
    int gate = tid >> 5, lane = tid & 31;
    int unit = chunk * 32 + lane;
    int grow = gate * Hq + unit;
    int seff = d ? (Sq - 1 - s) : s;
    const float* X = d ? g_Xb : g_Xf;
    const float* W = (d ? Whh_b : Whh_f) + (size_t)grow * Hq;
    float acc = X[((size_t)seff * Bq + b) * G4 + grow];
    const float4* W4 = (const float4*)W;
    const float4* h4 = (const float4*)hs;
#pragma unroll 8
    for (int k = 0; k < 128; k++) {
        float4 w = W4[k], h = h4[k];
        acc += w.x * h.x + w.y * h.y + w.z * h.z + w.w * h.w;
    }
    gv[tid] = acc;
    __syncthreads();
    if (tid < 32) {
        int u = chunk * 32 + tid;
        float iv = sigf(gv[tid]);
        float fv = sigf(gv[32 + tid]);
        float gg = tanhf(gv[64 + tid]);
        float ov = sigf(gv[96 + tid]);
        float c = g_cenc[d][b][u];
        c = fv * c + iv * gg;
        float h = ov * tanhf(c);
        g_cenc[d][b][u] = c;
        g_henc[slot ^ 1][d][b][u] = h;
        g_encout[b][seff][d * Hq + u] = h;
        g_encT[b][d * Hq + u][seff] = h;
    }
}

__global__ void k_dec_init() {
    int i = blockIdx.x * 256 + threadIdx.x;
    if (i < Bq * Hq) {
        ((float*)g_hdec)[i] = ((const float*)g_henc)[i];  // slot0, dir0 = final fwd h
        ((float*)g_cdec)[i] = ((const float*)g_cenc)[i];  // dir0 = final fwd c
    }
}

// ---------------- decoder: Q projection, k-split ----------------
__global__ void __launch_bounds__(256) k_qproj(int t, const float* __restrict__ att1_W) {
    __shared__ float hs[32][33];
    int tid = threadIdx.x;
    int jc = blockIdx.x, ks = blockIdx.y;
    int k0 = ks * 32;
    int slot = t & 1;
    {
        int b = tid >> 3, kk = (tid & 7) * 4;
        float4 v = *(const float4*)&g_hdec[slot][b][k0 + kk];
        hs[b][kk] = v.x; hs[b][kk + 1] = v.y; hs[b][kk + 2] = v.z; hs[b][kk + 3] = v.w;
    }
    __syncthreads();
    int j = jc * 128 + (tid & 127);
    int b0 = (tid >> 7) * 16;
    const float4* Wr = (const float4*)(att1_W + (size_t)j * H3 + H2 + k0);
    float acc[16];
#pragma unroll
    for (int b = 0; b < 16; b++) acc[b] = 0.f;
#pragma unroll
    for (int kg = 0; kg < 8; kg++) {
        float4 w = Wr[kg];
#pragma unroll
        for (int b = 0; b < 16; b++) {
            acc[b] += w.x * hs[b0 + b][kg * 4] + w.y * hs[b0 + b][kg * 4 + 1]
                    + w.z * hs[b0 + b][kg * 4 + 2] + w.w * hs[b0 + b][kg * 4 + 3];
        }
    }
#pragma unroll
    for (int b = 0; b < 16; b++) g_Qpart[ks][b0 + b][j] = acc[b];
}

// ---------------- decoder: scores + softmax + context ----------------
__global__ void __launch_bounds__(512) k_attn(int t, const float* __restrict__ att2_W) {
    __shared__ float Qs[H3];
    __shared__ float a2[H3];
    __shared__ float wsm[128];
    int b = blockIdx.x, tid = threadIdx.x;
    for (int j = tid; j < H3; j += 512) {
        a2[j] = att2_W[j];
        float q = 0.f;
#pragma unroll
        for (int p = 0; p < 16; p++) q += g_Qpart[p][b][j];
        Qs[j] = q;
    }
    __syncthreads();
    int warp = tid >> 5, lane = tid & 31;
    for (int s = warp; s < Sq; s += 16) {
        const float* Pp = g_P + ((size_t)b * Sq + s) * H3;
        float acc = 0.f;
        for (int j = lane; j < H3; j += 32) {
            float v = Pp[j] + Qs[j];
            acc += fmaxf(v, 0.f) * a2[j];
        }
#pragma unroll
        for (int o = 16; o; o >>= 1) acc += __shfl_xor_sync(0xffffffffu, acc, o);
        if (!lane) wsm[s] = acc;
    }
    __syncthreads();
    if (tid < 32) {
        float m = -1e30f;
        for (int s = tid; s < Sq; s += 32) m = fmaxf(m, wsm[s]);
#pragma unroll
        for (int o = 16; o; o >>= 1) m = fmaxf(m, __shfl_xor_sync(0xffffffffu, m, o));
        float e[4];
        float sum = 0.f;
        int i = 0;
        for (int s = tid; s < Sq; s += 32, i++) { e[i] = __expf(wsm[s] - m); sum += e[i]; }
#pragma unroll
        for (int o = 16; o; o >>= 1) sum += __shfl_xor_sync(0xffffffffu, sum, o);
        float inv = 1.f / sum;
        i = 0;
        for (int s = tid; s < Sq; s += 32, i++) wsm[s] = e[i] * inv;
    }
    __syncthreads();
    for (int k = tid; k < H2; k += 512) {
        const float* eT = &g_encT[b][k][0];
        float acc = 0.f;
#pragma unroll 4
        for (int s = 0; s < Sq; s++) acc += wsm[s] * eT[s];
        g_ctxs[t][b][k] = acc;
    }
}

// ---------------- decoder: fused LSTM gates + state update ----------------
__global__ void __launch_bounds__(128) k_dec_lstm(int t,
    const float* __restrict__ Wih, const float* __restrict__ Whh)
{
    __shared__ float xs[H2 + Hq];   // ctx (1024) then h (512)
    __shared__ float gv[128];
    int chunk = blockIdx.x, b = blockIdx.y, tid = threadIdx.x;
    int slot = t & 1;
    {
        const float4* c4 = (const float4*)&g_ctxs[t][b][0];
        float4* s4 = (float4*)xs;
        s4[tid] = c4[tid];
        s4[128 + tid] = c4[128 + tid];
        s4[256 + tid] = ((const float4*)&g_hdec[slot][b][0])[tid];
    }
    __syncthreads();
    int gate = tid >> 5, lane = tid & 31;
    int unit = chunk * 32 + lane;
    int grow = gate * Hq + unit;
    float acc = g_Xdec[((size_t)t * Bq + b) * G4 + grow];
    const float4* Wi4 = (const float4*)(Wih + (size_t)grow * H3 + Eq);
    const float4* x4 = (const float4*)xs;
#pragma unroll 8
    for (int k = 0; k < 256; k++) {
        float4 w = Wi4[k], x = x4[k];
        acc += w.x * x.x + w.y * x.y + w.z * x.z + w.w * x.w;
    }
    const float4* Wh4 = (const float4*)(Whh + (size_t)grow * Hq);
#pragma unroll 8
    for (int k = 0; k < 128; k++) {
        float4 w = Wh4[k], x = x4[256 + k];
        acc += w.x * x.x + w.y * x.y + w.z * x.z + w.w * x.w;
    }
    gv[tid] = acc;
    __syncthreads();
    if (tid < 32) {
        int u = chunk * 32 + tid;
        float iv = sigf(gv[tid]);
        float fv = sigf(gv[32 + tid]);
        float gg = tanhf(gv[64 + tid]);
        float ov = sigf(gv[96 + tid]);
        float c = g_cdec[b][u];
        c = fv * c + iv * gg;
        float h = ov * tanhf(c);
        g_cdec[b][u] = c;
        g_hdec[slot ^ 1][b][u] = h;
        g_decs[t][b][u] = h;
    }
}

// ---------------- classifier input pack ----------------
__global__ void k_pack() {
    int m = blockIdx.x;            // m = b*T + t
    int b = m / Tq, t = m % Tq;
    int tid = threadIdx.x;         // 128
    float4* dst = (float4*)(g_clsin + (size_t)m * 2048);
    dst[tid]       = ((const float4*)&g_temb[b][t][0])[tid];
    dst[128 + tid] = ((const float4*)&g_ctxs[t][b][0])[tid];
    dst[256 + tid] = ((const float4*)&g_ctxs[t][b][0])[128 + tid];
    dst[384 + tid] = ((const float4*)&g_decs[t][b][0])[tid];
}

// ---------------- host ----------------
extern "C" void kernel_launch(void* const* d_in, const int* in_sizes, int n_in,
                              void* d_out, int out_size) {
    (void)in_sizes; (void)n_in; (void)out_size;
    const int*   src       = (const int*)d_in[0];
    const int*   tgt       = (const int*)d_in[1];
    const float* src_emb   = (const float*)d_in[2];
    const float* tgt_emb   = (const float*)d_in[3];
    const float* eWih_f    = (const float*)d_in[4];
    const float* eWhh_f    = (const float*)d_in[5];
    const float* ebih_f    = (const float*)d_in[6];
    const float* ebhh_f    = (const float*)d_in[7];
    const float* eWih_b    = (const float*)d_in[8];
    const float* eWhh_b    = (const float*)d_in[9];
    const float* ebih_b    = (const float*)d_in[10];
    const float* ebhh_b    = (const float*)d_in[11];
    const float* dWih      = (const float*)d_in[12];
    const float* dWhh      = (const float*)d_in[13];
    const float* dbih      = (const float*)d_in[14];
    const float* dbhh      = (const float*)d_in[15];
    const float* att1_W    = (const float*)d_in[16];
    const float* att1_b    = (const float*)d_in[17];
    const float* att2_W    = (const float*)d_in[18];
    const float* cls1_W    = (const float*)d_in[20];
    const float* cls1_b    = (const float*)d_in[21];
    const float* cls2_W    = (const float*)d_in[22];
    const float* cls2_b    = (const float*)d_in[23];
    float* out = (float*)d_out;

    float *p_xsrc, *p_Xf, *p_Xb, *p_encout, *p_P, *p_temb_tb, *p_Xdec, *p_clsin, *p_hid;
    cudaGetSymbolAddress((void**)&p_xsrc, g_xsrc);
    cudaGetSymbolAddress((void**)&p_Xf, g_Xf);
    cudaGetSymbolAddress((void**)&p_Xb, g_Xb);
    cudaGetSymbolAddress((void**)&p_encout, g_encout);
    cudaGetSymbolAddress((void**)&p_P, g_P);
    cudaGetSymbolAddress((void**)&p_temb_tb, g_temb_tb);
    cudaGetSymbolAddress((void**)&p_Xdec, g_Xdec);
    cudaGetSymbolAddress((void**)&p_clsin, g_clsin);
    cudaGetSymbolAddress((void**)&p_hid, g_hid);

    k_zero_state<<<256, 256>>>();
    k_gather_src<<<Sq * Bq, 128>>>(src, src_emb);
    k_gather_tgt<<<Bq * Tq, 128>>>(tgt, tgt_emb);

    // encoder input gate precompute: [3200,512] x [2048,512]^T
    k_mma<<<dim3(25, 16), 256>>>(p_xsrc, Eq, eWih_f, Eq, ebih_f, ebhh_f,
                                 p_Xf, G4, Sq * Bq, G4, Eq, 0);
    k_mma<<<dim3(25, 16), 256>>>(p_xsrc, Eq, eWih_b, Eq, ebih_b, ebhh_b,
                                 p_Xb, G4, Sq * Bq, G4, Eq, 0);

    for (int s = 0; s < Sq; s++)
        k_enc_step<<<dim3(16, 32, 2), 128>>>(s, eWhh_f, eWhh_b);

    // attention layer-1 enc part, hoisted: [3200,1024] x [1536 rows, first 1024 cols]^T
    k_mma<<<dim3(25, 12), 256>>>(p_encout, H2, att1_W, H3, att1_b, (const float*)nullptr,
                                 p_P, H3, Bq * Sq, H3, H2, 0);

    // decoder input gate precompute (embedding part)
    k_mma<<<dim3(25, 16), 256>>>(p_temb_tb, Eq, dWih, H3, dbih, dbhh,
                                 p_Xdec, G4, Tq * Bq, G4, Eq, 0);

    k_dec_init<<<64, 256>>>();

    for (int t = 0; t < Tq; t++) {
        k_qproj<<<dim3(12, 16), 256>>>(t, att1_W);
        k_attn<<<32, 512>>>(t, att2_W);
        k_dec_lstm<<<dim3(16, 32), 128>>>(t, dWih, dWhh);
    }

    k_pack<<<Bq * Tq, 128>>>();

    // classifier
    k_mma<<<dim3(25, 8), 256>>>(p_clsin, 2048, cls1_W, 2048, cls1_b, (const float*)nullptr,
                                p_hid, H2, Bq * Tq, H2, 2048, 1);
    k_mma<<<dim3(25, 250), 256>>>(p_hid, H2, cls2_W, H2, cls2_b, (const float*)nullptr,
                                  out, VTq, Bq * Tq, VTq, H2, 0);
}